// round 3
// baseline (speedup 1.0000x reference)
#include <cuda_runtime.h>

// GraphSAGE 3-layer GCN aggregator. N=100000, E=1600000, 64->64->64->40.
//
// Restructure: ((segsum(h[src]) + h) * inv) @ W^T + b
//            = (segsum(p[src])  + p) * inv + b   with p = h @ W^T
// Pipeline (per call):
//   deg -> exclusive scan -> CSR fill (esrc sorted by dst)
//   k0: p0 = feats @ W0^T
//   k1: h1 = relu((gather p0 + self)*inv + b0); p1 = h1 @ W1^T   (fused)
//   k2: h2 = relu((gather p1 + self)*inv + b1); p2 = h2 @ W2^T   (fused)
//   k3: out = (gather p2 + self)*inv + b2                         (no proj)
// Gather is CSR-based (no atomics): 16 lanes/node, float4/lane.

constexpr int NN = 100000;
constexpr int NE = 1600000;
constexpr int NB = (NN + 1023) / 1024;  // 98 scan blocks

__device__ float g_pA[NN * 64];
__device__ float g_pB[NN * 64];
__device__ int   g_deg[NN];
__device__ int   g_off[NN + 1];
__device__ int   g_cur[NN];
__device__ int   g_esrc[NE];
__device__ int   g_bsum[NB];
__device__ int   g_boff[NB];

// ---------------------------------------------------------------- degrees ---
__global__ void deg_zero_k() {
    int i = blockIdx.x * 256 + threadIdx.x;
    if (i < NN) g_deg[i] = 0;
}

__global__ void deg_count_k(const int* __restrict__ dst) {
    int i = blockIdx.x * 256 + threadIdx.x;
    if (i < NE) atomicAdd(&g_deg[dst[i]], 1);
}

// ------------------------------------------------------------------- scan ---
__global__ __launch_bounds__(1024) void scan_bsum_k() {
    int i = blockIdx.x * 1024 + threadIdx.x;
    int v = (i < NN) ? g_deg[i] : 0;
#pragma unroll
    for (int o = 16; o; o >>= 1) v += __shfl_down_sync(~0u, v, o);
    __shared__ int ws[32];
    if ((threadIdx.x & 31) == 0) ws[threadIdx.x >> 5] = v;
    __syncthreads();
    if (threadIdx.x < 32) {
        int s = ws[threadIdx.x];
#pragma unroll
        for (int o = 16; o; o >>= 1) s += __shfl_down_sync(~0u, s, o);
        if (threadIdx.x == 0) g_bsum[blockIdx.x] = s;
    }
}

__global__ void scan_partials_k() {  // 1 block x 128 (NB=98 <= 128)
    int t = threadIdx.x;
    int v = (t < NB) ? g_bsum[t] : 0;
    int lane = t & 31, w = t >> 5;
    int x = v;
#pragma unroll
    for (int o = 1; o < 32; o <<= 1) {
        int y = __shfl_up_sync(~0u, x, o);
        if (lane >= o) x += y;
    }
    __shared__ int wsum[4];
    if (lane == 31) wsum[w] = x;
    __syncthreads();
    int add = 0;
    for (int j = 0; j < w; j++) add += wsum[j];
    if (t < NB) g_boff[t] = x + add - v;  // exclusive
}

__global__ __launch_bounds__(1024) void scan_write_k() {
    int i = blockIdx.x * 1024 + threadIdx.x;
    int v = (i < NN) ? g_deg[i] : 0;
    int lane = threadIdx.x & 31, w = threadIdx.x >> 5;
    int x = v;
#pragma unroll
    for (int o = 1; o < 32; o <<= 1) {
        int y = __shfl_up_sync(~0u, x, o);
        if (lane >= o) x += y;
    }
    __shared__ int ws[32], sws[32];
    if (lane == 31) ws[w] = x;
    __syncthreads();
    if (threadIdx.x < 32) {
        int s = ws[threadIdx.x];
        int xx = s;
#pragma unroll
        for (int o = 1; o < 32; o <<= 1) {
            int y = __shfl_up_sync(~0u, xx, o);
            if (lane >= o) xx += y;
        }
        sws[threadIdx.x] = xx - s;  // exclusive warp prefix
    }
    __syncthreads();
    int incl = x + sws[w] + g_boff[blockIdx.x];
    int excl = incl - v;
    if (i < NN) {
        g_off[i] = excl;
        g_cur[i] = excl;
        if (i == NN - 1) g_off[NN] = incl;
    }
}

// ------------------------------------------------------------------- fill ---
__global__ void fill_k(const int* __restrict__ src, const int* __restrict__ dst) {
    int e = blockIdx.x * 256 + threadIdx.x;
    if (e < NE) {
        int d = dst[e];
        int pos = atomicAdd(&g_cur[d], 1);
        g_esrc[pos] = src[e];
    }
}

// ------------------------------------------------------------------- gemm ---
// p[n,o] = sum_k h[n,k] * W[o,k]  (k0: initial projection of raw features)
__global__ __launch_bounds__(512) void gemm_k(const float* __restrict__ h,
                                              const float* __restrict__ W,
                                              float* __restrict__ p) {
    __shared__ float Ws[64 * 65];
    __shared__ float hs[8][64];
    const int tx = threadIdx.x, ty = threadIdx.y;
    const int tid = ty * 64 + tx;
    for (int i = tid; i < 64 * 64; i += 512)
        Ws[(i >> 6) * 65 + (i & 63)] = W[i];
    __syncthreads();
    float w[64];
#pragma unroll
    for (int k = 0; k < 64; k++) w[k] = Ws[tx * 65 + k];

    const int base = blockIdx.x * 64;
#pragma unroll
    for (int it = 0; it < 8; it++) {
        int n = base + it * 8 + ty;
        __syncthreads();
        if (n < NN) hs[ty][tx] = h[n * 64 + tx];
        __syncthreads();
        if (n < NN) {
            float acc = 0.f;
#pragma unroll
            for (int k = 0; k < 64; k++) acc = fmaf(hs[ty][k], w[k], acc);
            p[n * 64 + tx] = acc;
        }
    }
}

// ---------------------------------------------------------- fused layer -----
// Per node: gather-sum p[src] rows (CSR), + self, *inv, +b, (relu),
// then optionally project h @ W^T -> pout (width DO). If DO==0, write h (width
// DG) straight to pout. 256 threads = 16 node-groups x 16 lanes, float4/lane.
template <int DG, int DO, bool RELU>
__global__ __launch_bounds__(256) void layer_k(const float* __restrict__ bv,
                                               const float* __restrict__ W,
                                               const float* __restrict__ pin,
                                               float* __restrict__ pout) {
    constexpr int L4 = DG / 4;
    __shared__ __align__(16) float Ws[64 * 65];
    __shared__ __align__(16) float hs[16][68];
    const int tid = threadIdx.x;

    if (DO > 0) {
        for (int i = tid; i < DO * 64; i += 256)
            Ws[(i >> 6) * 65 + (i & 63)] = W[i];
    }

    const int g = tid >> 4;
    const int q = tid & 15;
    const int node = blockIdx.x * 16 + g;
    const float4* pin4 = reinterpret_cast<const float4*>(pin);

    if (node < NN && q < L4) {
        int s0 = g_off[node], s1 = g_off[node + 1];
        float inv = 1.f / (float)(s1 - s0 + 1);
        float4 a0 = __ldg(&pin4[node * L4 + q]);  // self term
        float4 a1 = make_float4(0.f, 0.f, 0.f, 0.f);
        int e = s0;
        for (; e + 1 < s1; e += 2) {
            int sa = __ldg(&g_esrc[e]);
            int sb = __ldg(&g_esrc[e + 1]);
            float4 va = __ldg(&pin4[sa * L4 + q]);
            float4 vb = __ldg(&pin4[sb * L4 + q]);
            a0.x += va.x; a0.y += va.y; a0.z += va.z; a0.w += va.w;
            a1.x += vb.x; a1.y += vb.y; a1.z += vb.z; a1.w += vb.w;
        }
        if (e < s1) {
            int sa = __ldg(&g_esrc[e]);
            float4 va = __ldg(&pin4[sa * L4 + q]);
            a0.x += va.x; a0.y += va.y; a0.z += va.z; a0.w += va.w;
        }
        a0.x += a1.x; a0.y += a1.y; a0.z += a1.z; a0.w += a1.w;
        float4 bb = __ldg(&reinterpret_cast<const float4*>(bv)[q]);
        float4 r;
        r.x = fmaf(a0.x, inv, bb.x);
        r.y = fmaf(a0.y, inv, bb.y);
        r.z = fmaf(a0.z, inv, bb.z);
        r.w = fmaf(a0.w, inv, bb.w);
        if (RELU) {
            r.x = fmaxf(r.x, 0.f); r.y = fmaxf(r.y, 0.f);
            r.z = fmaxf(r.z, 0.f); r.w = fmaxf(r.w, 0.f);
        }
        if (DO == 0) {
            reinterpret_cast<float4*>(pout)[node * L4 + q] = r;
        } else {
            reinterpret_cast<float4*>(&hs[g][0])[q] = r;
        }
    }

    if (DO > 0) {
        __syncthreads();
        constexpr int TOT = 16 * DO;
#pragma unroll
        for (int r = 0; r < (TOT + 255) / 256; r++) {
            int oi = r * 256 + tid;
            if (oi < TOT) {
                int gg = oi / DO;
                int o = oi - gg * DO;
                int gn = blockIdx.x * 16 + gg;
                if (gn < NN) {
                    float acc = 0.f;
#pragma unroll
                    for (int k = 0; k < 64; k++)
                        acc = fmaf(hs[gg][k], Ws[o * 65 + k], acc);
                    pout[gn * DO + o] = acc;
                }
            }
        }
    }
}

// ----------------------------------------------------------------- launch ---
extern "C" void kernel_launch(void* const* d_in, const int* in_sizes, int n_in,
                              void* d_out, int out_size) {
    const float* feats = (const float*)d_in[0];
    const int*   src   = (const int*)d_in[1];
    const int*   dst   = (const int*)d_in[2];
    const float* W0 = (const float*)d_in[3];
    const float* b0 = (const float*)d_in[4];
    const float* W1 = (const float*)d_in[5];
    const float* b1 = (const float*)d_in[6];
    const float* W2 = (const float*)d_in[7];
    const float* b2 = (const float*)d_in[8];
    float* out = (float*)d_out;

    void *pA_v = nullptr, *pB_v = nullptr;
    cudaGetSymbolAddress(&pA_v, g_pA);
    cudaGetSymbolAddress(&pB_v, g_pB);
    float* pA = (float*)pA_v;
    float* pB = (float*)pB_v;

    // CSR build
    deg_zero_k<<<(NN + 255) / 256, 256>>>();
    deg_count_k<<<(NE + 255) / 256, 256>>>(dst);
    scan_bsum_k<<<NB, 1024>>>();
    scan_partials_k<<<1, 128>>>();
    scan_write_k<<<NB, 1024>>>();
    fill_k<<<(NE + 255) / 256, 256>>>(src, dst);

    const int GB_L = (NN + 15) / 16;  // 6250

    // k0: p0 = feats @ W0^T
    gemm_k<<<(NN + 63) / 64, dim3(64, 8)>>>(feats, W0, pA);
    // k1: h1 = relu(agg(p0)*inv + b0); p1 = h1 @ W1^T
    layer_k<64, 64, true><<<GB_L, 256>>>(b0, W1, pA, pB);
    // k2: h2 = relu(agg(p1)*inv + b1); p2 = h2 @ W2^T (40-wide)
    layer_k<64, 40, true><<<GB_L, 256>>>(b1, W2, pB, pA);
    // k3: out = agg(p2)*inv + b2
    layer_k<40, 0, false><<<GB_L, 256>>>(b2, nullptr, pA, out);
}